// round 12
// baseline (speedup 1.0000x reference)
#include <cuda_runtime.h>

// ---------------------------------------------------------------------------
// TrustGNN: GATv2 conv (with mean-pooled self-loop edge attrs) + edge MLP
// Self-loop edge features computed via linearity of the edge projection:
//   ee_self[n] = segment_sum(ee_edges, tgt)[n] / max(cnt[n],1)
// ---------------------------------------------------------------------------
#define NNODES   50000
#define E0       800000
#define EAUG     (E0 + NNODES)
#define NODE_F   388
#define EDGE_F   385
#define NEG_SLOPE 0.2f

#define BM 128
#define BN 64
#define BK 16
#define TM 8
#define TN 8

// ---------------- scratch (device globals: allocation-free) ----------------
__device__ float        g_cnt[NNODES];
__device__ float        g_xlr[(size_t)NNODES * 128];       // [xl | xr]
__device__ float        g_ee[(size_t)EAUG * 64];           // ea_aug @ lin_e_w
__device__ float        g_sc[(size_t)EAUG * 2];            // score -> exp(score-max)
__device__ unsigned int g_smax[NNODES * 2];                // ordered-uint encoded max
__device__ float        g_ssum[NNODES * 2];
__device__ float        g_out[NNODES * 64];
__device__ float        g_h[NNODES * 64];                  // relu(conv out)

__device__ __forceinline__ unsigned int ford(float f) {
    unsigned int u = __float_as_uint(f);
    return (u & 0x80000000u) ? ~u : (u | 0x80000000u);
}
__device__ __forceinline__ float fdec(unsigned int u) {
    u = (u & 0x80000000u) ? (u & 0x7FFFFFFFu) : ~u;
    return __uint_as_float(u);
}

// ---------------- init: zero accumulators, set smax to -inf ----------------
__global__ void k_init() {
    int stride = gridDim.x * blockDim.x;
    for (int idx = blockIdx.x * blockDim.x + threadIdx.x;
         idx < NNODES * 64; idx += stride) {
        g_out[idx] = 0.f;
        g_ee[(size_t)E0 * 64 + idx] = 0.f;      // self-loop ee accumulator
        if (idx < NNODES)     g_cnt[idx] = 0.f;
        if (idx < NNODES * 2) { g_smax[idx] = 0x00800000u; g_ssum[idx] = 0.f; }
    }
}

// ---------------- tiled SGEMM, 3 modes -------------------------------------
// MODE 0: x(NN x 388) @ [lin_l_w | lin_r_w]  -> g_xlr (NN x 128), + bias
// MODE 1: edge_attr(E0 x 385) @ lin_e_w      -> g_ee[0:E0] (x 64)
// MODE 2: [h[src]|h[tgt]|q](E0 x 512) @ mlp1_w, relu+bias, then fused
//         mlp2 + softmax -> trust (d_out)
template <int MODE>
__global__ void __launch_bounds__(128)
k_gemm(const float* __restrict__ A,     // mode0: x
       const float* __restrict__ ea,    // edge_attr
       const int*   __restrict__ src,
       const int*   __restrict__ tgt,
       const float* __restrict__ Bl,    // weight K x 64
       const float* __restrict__ Br,    // mode0: second 64 cols
       const float* __restrict__ bl,    // bias (mode0: left; mode2: mlp1_b)
       const float* __restrict__ br,    // mode0: right bias
       const float* __restrict__ w2,    // mode2: mlp2_w (64x3)
       const float* __restrict__ b2,    // mode2: mlp2_b (3)
       float* __restrict__ C,           // mode2: trust out
       int M, int K)
{
    __shared__ float As[BK][BM + 4];
    __shared__ float Bs[BK][BN];
    __shared__ int   s_src[(MODE == 2) ? BM : 1];
    __shared__ int   s_tgt[(MODE == 2) ? BM : 1];
    __shared__ float Hs[(MODE == 2) ? BM : 1][(MODE == 2) ? (BN + 1) : 1];

    const int tid = threadIdx.x;
    const int tx  = tid & 7;    // col group (8 groups of 8)
    const int ty  = tid >> 3;   // row group (16 groups of 8)
    const int row0 = blockIdx.x * BM;

    const float* Bw   = (MODE == 0 && blockIdx.y == 1) ? Br : Bl;
    const float* bias = (MODE == 0) ? ((blockIdx.y == 1) ? br : bl) : bl;

    if (MODE == 2) {
        for (int i = tid; i < BM; i += 128) {
            int r = row0 + i;
            s_src[i] = (r < M) ? src[r] : 0;
            s_tgt[i] = (r < M) ? tgt[r] : 0;
        }
        __syncthreads();
    }

    float acc[TM][TN];
#pragma unroll
    for (int i = 0; i < TM; i++)
#pragma unroll
        for (int j = 0; j < TN; j++) acc[i][j] = 0.f;

    const int nk = (K + BK - 1) / BK;
    for (int kt = 0; kt < nk; kt++) {
        const int k0 = kt * BK;
        // stage A tile: BM x BK = 2048 elems, 16 per thread
#pragma unroll
        for (int i = 0; i < (BM * BK) / 128; i++) {
            int lin = i * 128 + tid;
            int m  = lin >> 4;
            int kk = lin & 15;
            int r = row0 + m;
            int k = k0 + kk;
            float v = 0.f;
            if (r < M && k < K) {
                if (MODE == 0) {
                    v = A[(size_t)r * NODE_F + k];
                } else if (MODE == 1) {
                    v = ea[(size_t)r * EDGE_F + k];
                } else {
                    if (k < 64)       v = g_h[s_src[m] * 64 + k];
                    else if (k < 128) v = g_h[s_tgt[m] * 64 + (k - 64)];
                    else              v = ea[(size_t)r * EDGE_F + (k - 128)];
                }
            }
            As[kk][m] = v;
        }
        // stage B tile: BK x BN = 1024 elems, 8 per thread
#pragma unroll
        for (int i = 0; i < (BK * BN) / 128; i++) {
            int lin = i * 128 + tid;
            int kk = lin >> 6;
            int n  = lin & 63;
            int k = k0 + kk;
            Bs[kk][n] = (k < K) ? Bw[(size_t)k * 64 + n] : 0.f;
        }
        __syncthreads();

#pragma unroll
        for (int kk = 0; kk < BK; kk++) {
            float a[TM], b[TN];
            float4 a0 = *(const float4*)&As[kk][ty * TM];
            float4 a1 = *(const float4*)&As[kk][ty * TM + 4];
            a[0]=a0.x; a[1]=a0.y; a[2]=a0.z; a[3]=a0.w;
            a[4]=a1.x; a[5]=a1.y; a[6]=a1.z; a[7]=a1.w;
            float4 b0 = *(const float4*)&Bs[kk][tx * TN];
            float4 b1 = *(const float4*)&Bs[kk][tx * TN + 4];
            b[0]=b0.x; b[1]=b0.y; b[2]=b0.z; b[3]=b0.w;
            b[4]=b1.x; b[5]=b1.y; b[6]=b1.z; b[7]=b1.w;
#pragma unroll
            for (int i = 0; i < TM; i++)
#pragma unroll
                for (int j = 0; j < TN; j++)
                    acc[i][j] += a[i] * b[j];
        }
        __syncthreads();
    }

    if (MODE == 0) {
        const int cbase = blockIdx.y * 64;
#pragma unroll
        for (int i = 0; i < TM; i++) {
            int r = row0 + ty * TM + i;
            if (r < M) {
#pragma unroll
                for (int j = 0; j < TN; j++) {
                    int c = tx * TN + j;
                    g_xlr[(size_t)r * 128 + cbase + c] = acc[i][j] + bias[c];
                }
            }
        }
    } else if (MODE == 1) {
#pragma unroll
        for (int i = 0; i < TM; i++) {
            int r = row0 + ty * TM + i;
            if (r < M) {
#pragma unroll
                for (int j = 0; j < TN; j++)
                    g_ee[(size_t)r * 64 + tx * TN + j] = acc[i][j];
            }
        }
    } else {
        // hidden = relu(acc + b1) -> smem, then fused mlp2 + softmax + trust
#pragma unroll
        for (int i = 0; i < TM; i++) {
            int m = ty * TM + i;
#pragma unroll
            for (int j = 0; j < TN; j++) {
                int c = tx * TN + j;
                Hs[m][c] = fmaxf(acc[i][j] + bias[c], 0.f);
            }
        }
        __syncthreads();
        int r = row0 + tid;
        if (r < M) {
            float l0 = __ldg(&b2[0]), l1 = __ldg(&b2[1]), l2 = __ldg(&b2[2]);
#pragma unroll 8
            for (int j = 0; j < 64; j++) {
                float hv = Hs[tid][j];
                l0 += hv * __ldg(&w2[j * 3 + 0]);
                l1 += hv * __ldg(&w2[j * 3 + 1]);
                l2 += hv * __ldg(&w2[j * 3 + 2]);
            }
            float mx = fmaxf(l0, fmaxf(l1, l2));
            float e0 = __expf(l0 - mx), e1 = __expf(l1 - mx), e2 = __expf(l2 - mx);
            C[r] = (0.5f * e1 + e2) / (e0 + e1 + e2);
        }
    }
}

// ---- self-loop ee: segment-sum projected edge features (warp per edge) ----
__global__ void k_loopee(const int* __restrict__ tgt) {
    int e = (blockIdx.x * blockDim.x + threadIdx.x) >> 5;
    int lane = threadIdx.x & 31;
    if (e >= E0) return;
    int t = tgt[e];
    const float* row = g_ee + (size_t)e * 64;
    float* dst = g_ee + (size_t)(E0 + t) * 64;
    atomicAdd(&dst[lane],      row[lane]);
    atomicAdd(&dst[lane + 32], row[lane + 32]);
    if (lane == 0) atomicAdd(&g_cnt[t], 1.0f);
}

__global__ void k_selfdiv() {
    int idx = blockIdx.x * blockDim.x + threadIdx.x;
    if (idx >= NNODES * 64) return;
    int n = idx >> 6;
    g_ee[(size_t)E0 * 64 + idx] /= fmaxf(g_cnt[n], 1.0f);
}

// ---------------- attention score + segment max (warp per aug. edge) -------
__global__ void k_score(const int* __restrict__ src, const int* __restrict__ tgt,
                        const float* __restrict__ att) {
    int e = (blockIdx.x * blockDim.x + threadIdx.x) >> 5;
    int lane = threadIdx.x & 31;
    if (e >= EAUG) return;
    int s, t;
    if (e < E0) { s = src[e]; t = tgt[e]; } else { s = e - E0; t = s; }
    const float* xl = g_xlr + (size_t)s * 128;
    const float* xr = g_xlr + (size_t)t * 128 + 64;
    const float* ee = g_ee  + (size_t)e * 64;
    int j1 = lane, j2 = lane + 32;
    float v1 = xl[j1] + xr[j1] + ee[j1];
    float v2 = xl[j2] + xr[j2] + ee[j2];
    v1 = (v1 > 0.f) ? v1 : NEG_SLOPE * v1;
    v2 = (v2 > 0.f) ? v2 : NEG_SLOPE * v2;
    float p1 = __ldg(&att[j1]) * v1;   // head 0
    float p2 = __ldg(&att[j2]) * v2;   // head 1
#pragma unroll
    for (int o = 16; o > 0; o >>= 1) {
        p1 += __shfl_down_sync(0xFFFFFFFFu, p1, o);
        p2 += __shfl_down_sync(0xFFFFFFFFu, p2, o);
    }
    if (lane == 0) {
        g_sc[(size_t)e * 2 + 0] = p1;
        g_sc[(size_t)e * 2 + 1] = p2;
        atomicMax(&g_smax[t * 2 + 0], ford(p1));
        atomicMax(&g_smax[t * 2 + 1], ford(p2));
    }
}

// ---------------- exp(score - max) + segment sum ---------------------------
__global__ void k_expsum(const int* __restrict__ tgt) {
    int i = blockIdx.x * blockDim.x + threadIdx.x;
    if (i >= EAUG * 2) return;
    int e = i >> 1, hd = i & 1;
    int t = (e < E0) ? tgt[e] : e - E0;
    float ex = __expf(g_sc[i] - fdec(g_smax[t * 2 + hd]));
    g_sc[i] = ex;
    atomicAdd(&g_ssum[t * 2 + hd], ex);
}

// ---------------- alpha-weighted aggregation (warp per aug. edge) ----------
__global__ void k_agg(const int* __restrict__ src, const int* __restrict__ tgt) {
    int e = (blockIdx.x * blockDim.x + threadIdx.x) >> 5;
    int lane = threadIdx.x & 31;
    if (e >= EAUG) return;
    int s, t;
    if (e < E0) { s = src[e]; t = tgt[e]; } else { s = e - E0; t = s; }
    float a0 = g_sc[(size_t)e * 2 + 0] / (g_ssum[t * 2 + 0] + 1e-16f);
    float a1 = g_sc[(size_t)e * 2 + 1] / (g_ssum[t * 2 + 1] + 1e-16f);
    const float* xl = g_xlr + (size_t)s * 128;
    atomicAdd(&g_out[t * 64 + lane],      a0 * xl[lane]);
    atomicAdd(&g_out[t * 64 + 32 + lane], a1 * xl[32 + lane]);
}

// ---------------- h = relu(out + conv_b) -----------------------------------
__global__ void k_nodeh(const float* __restrict__ conv_b) {
    int i = blockIdx.x * blockDim.x + threadIdx.x;
    if (i >= NNODES * 64) return;
    g_h[i] = fmaxf(g_out[i] + __ldg(&conv_b[i & 63]), 0.f);
}

// ---------------------------------------------------------------------------
extern "C" void kernel_launch(void* const* d_in, const int* in_sizes, int n_in,
                              void* d_out, int out_size) {
    const float* x   = (const float*)d_in[0];
    const int*   ei  = (const int*)  d_in[1];
    const float* ea  = (const float*)d_in[2];
    const float* llw = (const float*)d_in[3];
    const float* llb = (const float*)d_in[4];
    const float* lrw = (const float*)d_in[5];
    const float* lrb = (const float*)d_in[6];
    const float* lew = (const float*)d_in[7];
    const float* att = (const float*)d_in[8];
    const float* cb  = (const float*)d_in[9];
    const float* w1  = (const float*)d_in[10];
    const float* b1  = (const float*)d_in[11];
    const float* w2  = (const float*)d_in[12];
    const float* b2  = (const float*)d_in[13];
    float* out = (float*)d_out;

    const int* src = ei;
    const int* tgt = ei + E0;

    k_init<<<2048, 256>>>();

    // xl | xr
    k_gemm<0><<<dim3((NNODES + BM - 1) / BM, 2), 128>>>(
        x, nullptr, nullptr, nullptr, llw, lrw, llb, lrb,
        nullptr, nullptr, nullptr, NNODES, NODE_F);

    // ee over real edges only
    k_gemm<1><<<dim3((E0 + BM - 1) / BM, 1), 128>>>(
        nullptr, ea, nullptr, nullptr, lew, nullptr, nullptr, nullptr,
        nullptr, nullptr, nullptr, E0, EDGE_F);

    // self-loop ee via linearity of the projection
    k_loopee<<<(E0 * 32 + 255) / 256, 256>>>(tgt);
    k_selfdiv<<<(NNODES * 64 + 255) / 256, 256>>>();

    k_score<<<(EAUG * 32 + 255) / 256, 256>>>(src, tgt, att);
    k_expsum<<<(EAUG * 2 + 255) / 256, 256>>>(tgt);
    k_agg<<<(EAUG * 32 + 255) / 256, 256>>>(src, tgt);
    k_nodeh<<<(NNODES * 64 + 255) / 256, 256>>>(cb);

    // fused edge MLP -> trust
    k_gemm<2><<<dim3((E0 + BM - 1) / BM, 1), 128>>>(
        nullptr, ea, src, tgt, w1, nullptr, b1, nullptr,
        w2, b2, out, E0, 512);
}

// round 15
// speedup vs baseline: 1.7297x; 1.7297x over previous
#include <cuda_runtime.h>

// ---------------------------------------------------------------------------
// TrustGNN: GATv2 conv (with mean-pooled self-loop edge attrs) + edge MLP
// R13: (1) edge-MLP hidden decomposed:  [h_s|h_t|q]@W1 = (h@W1a)[s] + (h@W1b)[t] + q@W1c
//          -> per-node precompute (mode 3), mode-2 GEMM K: 512 -> 384
//      (2) BK=32 for modes 0/1/3 (fewer syncs); mode 2 keeps BK=16 (smem cap)
// ---------------------------------------------------------------------------
#define NNODES   50000
#define E0       800000
#define EAUG     (E0 + NNODES)
#define NODE_F   388
#define EDGE_F   385
#define NEG_SLOPE 0.2f

#define BM 128
#define BN 64
#define TM 8
#define TN 8

// ---------------- scratch (device globals: allocation-free) ----------------
__device__ float        g_cnt[NNODES];
__device__ float        g_xlr[(size_t)NNODES * 128];       // [xl | xr]
__device__ float        g_ee[(size_t)EAUG * 64];           // ea_aug @ lin_e_w
__device__ float        g_sc[(size_t)EAUG * 2];            // score -> exp(score-max)
__device__ unsigned int g_smax[NNODES * 2];                // ordered-uint encoded max
__device__ float        g_ssum[NNODES * 2];
__device__ float        g_out[NNODES * 64];
__device__ float        g_h[NNODES * 64];                  // relu(conv out)
__device__ float        g_p[(size_t)NNODES * 128];         // [h@W1a | h@W1b]

__device__ __forceinline__ unsigned int ford(float f) {
    unsigned int u = __float_as_uint(f);
    return (u & 0x80000000u) ? ~u : (u | 0x80000000u);
}
__device__ __forceinline__ float fdec(unsigned int u) {
    u = (u & 0x80000000u) ? (u & 0x7FFFFFFFu) : ~u;
    return __uint_as_float(u);
}

// ---------------- init: zero accumulators, set smax to -inf ----------------
__global__ void k_init() {
    int stride = gridDim.x * blockDim.x;
    for (int idx = blockIdx.x * blockDim.x + threadIdx.x;
         idx < NNODES * 64; idx += stride) {
        g_out[idx] = 0.f;
        g_ee[(size_t)E0 * 64 + idx] = 0.f;      // self-loop ee accumulator
        if (idx < NNODES)     g_cnt[idx] = 0.f;
        if (idx < NNODES * 2) { g_smax[idx] = 0x00800000u; g_ssum[idx] = 0.f; }
    }
}

// ---------------- tiled SGEMM, 4 modes -------------------------------------
// MODE 0: x(NN x 388) @ [lin_l_w | lin_r_w] -> g_xlr (NN x 128), + bias
// MODE 1: edge_attr(E0 x 385) @ lin_e_w     -> g_ee[0:E0] (x 64)
// MODE 3: g_h(NN x 64) @ [W1a | W1b]        -> g_p (NN x 128), no bias
// MODE 2: q(E0 x 384) @ W1c; epilogue hidden = relu(acc + pa[src]+pb[tgt]+b1),
//         then fused mlp2 + softmax -> trust (d_out)
template <int MODE>
__global__ void __launch_bounds__(128)
k_gemm(const float* __restrict__ A,     // mode0: x
       const float* __restrict__ ea,    // edge_attr
       const int*   __restrict__ src,
       const int*   __restrict__ tgt,
       const float* __restrict__ Bl,    // weight K x 64
       const float* __restrict__ Br,    // mode0/3: second 64 cols
       const float* __restrict__ bl,    // bias (mode0: left; mode2: mlp1_b)
       const float* __restrict__ br,    // mode0: right bias
       const float* __restrict__ w2,    // mode2: mlp2_w (64x3)
       const float* __restrict__ b2,    // mode2: mlp2_b (3)
       float* __restrict__ C,           // mode2: trust out
       int M, int K)
{
    constexpr int BKT = (MODE == 2) ? 16 : 32;

    __shared__ float As[BKT][BM + 4];
    __shared__ float Bs[BKT][BN];
    __shared__ int   s_src[(MODE == 2) ? BM : 1];
    __shared__ int   s_tgt[(MODE == 2) ? BM : 1];
    __shared__ float Hs[(MODE == 2) ? BM : 1][(MODE == 2) ? (BN + 1) : 1];

    const int tid = threadIdx.x;
    const int tx  = tid & 7;    // col group (8 groups of 8)
    const int ty  = tid >> 3;   // row group (16 groups of 8)
    const int row0 = blockIdx.x * BM;

    const float* Bw   = ((MODE == 0 || MODE == 3) && blockIdx.y == 1) ? Br : Bl;
    const float* bias = (MODE == 0) ? ((blockIdx.y == 1) ? br : bl) : bl;

    if (MODE == 2) {
        for (int i = tid; i < BM; i += 128) {
            int r = row0 + i;
            s_src[i] = (r < M) ? src[r] : 0;
            s_tgt[i] = (r < M) ? tgt[r] : 0;
        }
        __syncthreads();
    }

    float acc[TM][TN];
#pragma unroll
    for (int i = 0; i < TM; i++)
#pragma unroll
        for (int j = 0; j < TN; j++) acc[i][j] = 0.f;

    const int nk = (K + BKT - 1) / BKT;
    for (int kt = 0; kt < nk; kt++) {
        const int k0 = kt * BKT;
        // stage A tile: BM x BKT elems, (BM*BKT)/128 per thread
#pragma unroll
        for (int i = 0; i < (BM * BKT) / 128; i++) {
            int lin = i * 128 + tid;
            int m  = lin / BKT;
            int kk = lin % BKT;
            int r = row0 + m;
            int k = k0 + kk;
            float v = 0.f;
            if (r < M && k < K) {
                if (MODE == 0) {
                    v = A[(size_t)r * NODE_F + k];
                } else if (MODE == 1) {
                    v = ea[(size_t)r * EDGE_F + k];
                } else if (MODE == 3) {
                    v = g_h[(size_t)r * 64 + k];
                } else {
                    v = ea[(size_t)r * EDGE_F + k];   // q = edge_attr[:, :384]
                }
            }
            As[kk][m] = v;
        }
        // stage B tile: BKT x BN elems
#pragma unroll
        for (int i = 0; i < (BKT * BN) / 128; i++) {
            int lin = i * 128 + tid;
            int kk = lin >> 6;
            int n  = lin & 63;
            int k = k0 + kk;
            Bs[kk][n] = (k < K) ? Bw[(size_t)k * 64 + n] : 0.f;
        }
        __syncthreads();

#pragma unroll
        for (int kk = 0; kk < BKT; kk++) {
            float a[TM], b[TN];
            float4 a0 = *(const float4*)&As[kk][ty * TM];
            float4 a1 = *(const float4*)&As[kk][ty * TM + 4];
            a[0]=a0.x; a[1]=a0.y; a[2]=a0.z; a[3]=a0.w;
            a[4]=a1.x; a[5]=a1.y; a[6]=a1.z; a[7]=a1.w;
            float4 b0 = *(const float4*)&Bs[kk][tx * TN];
            float4 b1 = *(const float4*)&Bs[kk][tx * TN + 4];
            b[0]=b0.x; b[1]=b0.y; b[2]=b0.z; b[3]=b0.w;
            b[4]=b1.x; b[5]=b1.y; b[6]=b1.z; b[7]=b1.w;
#pragma unroll
            for (int i = 0; i < TM; i++)
#pragma unroll
                for (int j = 0; j < TN; j++)
                    acc[i][j] += a[i] * b[j];
        }
        __syncthreads();
    }

    if (MODE == 0) {
        const int cbase = blockIdx.y * 64;
#pragma unroll
        for (int i = 0; i < TM; i++) {
            int r = row0 + ty * TM + i;
            if (r < M) {
#pragma unroll
                for (int j = 0; j < TN; j++) {
                    int c = tx * TN + j;
                    g_xlr[(size_t)r * 128 + cbase + c] = acc[i][j] + bias[c];
                }
            }
        }
    } else if (MODE == 1) {
#pragma unroll
        for (int i = 0; i < TM; i++) {
            int r = row0 + ty * TM + i;
            if (r < M) {
#pragma unroll
                for (int j = 0; j < TN; j++)
                    g_ee[(size_t)r * 64 + tx * TN + j] = acc[i][j];
            }
        }
    } else if (MODE == 3) {
        const int cbase = blockIdx.y * 64;
#pragma unroll
        for (int i = 0; i < TM; i++) {
            int r = row0 + ty * TM + i;
            if (r < M) {
#pragma unroll
                for (int j = 0; j < TN; j++)
                    g_p[(size_t)r * 128 + cbase + tx * TN + j] = acc[i][j];
            }
        }
    } else {
        // hidden = relu(acc + pa[src] + pb[tgt] + b1) -> smem,
        // then fused mlp2 + softmax + trust
#pragma unroll
        for (int i = 0; i < TM; i++) {
            int m = ty * TM + i;
            const float* pa = g_p + (size_t)s_src[m] * 128 + tx * TN;
            const float* pb = g_p + (size_t)s_tgt[m] * 128 + 64 + tx * TN;
            float4 pa0 = *(const float4*)pa;
            float4 pa1 = *(const float4*)(pa + 4);
            float4 pb0 = *(const float4*)pb;
            float4 pb1 = *(const float4*)(pb + 4);
            float pav[TN] = {pa0.x,pa0.y,pa0.z,pa0.w,pa1.x,pa1.y,pa1.z,pa1.w};
            float pbv[TN] = {pb0.x,pb0.y,pb0.z,pb0.w,pb1.x,pb1.y,pb1.z,pb1.w};
#pragma unroll
            for (int j = 0; j < TN; j++) {
                int c = tx * TN + j;
                Hs[m][c] = fmaxf(acc[i][j] + pav[j] + pbv[j] + bias[c], 0.f);
            }
        }
        __syncthreads();
        int r = row0 + tid;
        if (r < M) {
            float l0 = __ldg(&b2[0]), l1 = __ldg(&b2[1]), l2 = __ldg(&b2[2]);
#pragma unroll 8
            for (int j = 0; j < 64; j++) {
                float hv = Hs[tid][j];
                l0 += hv * __ldg(&w2[j * 3 + 0]);
                l1 += hv * __ldg(&w2[j * 3 + 1]);
                l2 += hv * __ldg(&w2[j * 3 + 2]);
            }
            float mx = fmaxf(l0, fmaxf(l1, l2));
            float e0 = __expf(l0 - mx), e1 = __expf(l1 - mx), e2 = __expf(l2 - mx);
            C[r] = (0.5f * e1 + e2) / (e0 + e1 + e2);
        }
    }
}

// ---- self-loop ee: segment-sum projected edge features (warp per edge) ----
__global__ void k_loopee(const int* __restrict__ tgt) {
    int e = (blockIdx.x * blockDim.x + threadIdx.x) >> 5;
    int lane = threadIdx.x & 31;
    if (e >= E0) return;
    int t = tgt[e];
    const float* row = g_ee + (size_t)e * 64;
    float* dst = g_ee + (size_t)(E0 + t) * 64;
    atomicAdd(&dst[lane],      row[lane]);
    atomicAdd(&dst[lane + 32], row[lane + 32]);
    if (lane == 0) atomicAdd(&g_cnt[t], 1.0f);
}

__global__ void k_selfdiv() {
    int idx = blockIdx.x * blockDim.x + threadIdx.x;
    if (idx >= NNODES * 64) return;
    int n = idx >> 6;
    g_ee[(size_t)E0 * 64 + idx] /= fmaxf(g_cnt[n], 1.0f);
}

// ---------------- attention score + segment max (warp per aug. edge) -------
__global__ void k_score(const int* __restrict__ src, const int* __restrict__ tgt,
                        const float* __restrict__ att) {
    int e = (blockIdx.x * blockDim.x + threadIdx.x) >> 5;
    int lane = threadIdx.x & 31;
    if (e >= EAUG) return;
    int s, t;
    if (e < E0) { s = src[e]; t = tgt[e]; } else { s = e - E0; t = s; }
    const float* xl = g_xlr + (size_t)s * 128;
    const float* xr = g_xlr + (size_t)t * 128 + 64;
    const float* ee = g_ee  + (size_t)e * 64;
    int j1 = lane, j2 = lane + 32;
    float v1 = xl[j1] + xr[j1] + ee[j1];
    float v2 = xl[j2] + xr[j2] + ee[j2];
    v1 = (v1 > 0.f) ? v1 : NEG_SLOPE * v1;
    v2 = (v2 > 0.f) ? v2 : NEG_SLOPE * v2;
    float p1 = __ldg(&att[j1]) * v1;   // head 0
    float p2 = __ldg(&att[j2]) * v2;   // head 1
#pragma unroll
    for (int o = 16; o > 0; o >>= 1) {
        p1 += __shfl_down_sync(0xFFFFFFFFu, p1, o);
        p2 += __shfl_down_sync(0xFFFFFFFFu, p2, o);
    }
    if (lane == 0) {
        g_sc[(size_t)e * 2 + 0] = p1;
        g_sc[(size_t)e * 2 + 1] = p2;
        atomicMax(&g_smax[t * 2 + 0], ford(p1));
        atomicMax(&g_smax[t * 2 + 1], ford(p2));
    }
}

// ---------------- exp(score - max) + segment sum ---------------------------
__global__ void k_expsum(const int* __restrict__ tgt) {
    int i = blockIdx.x * blockDim.x + threadIdx.x;
    if (i >= EAUG * 2) return;
    int e = i >> 1, hd = i & 1;
    int t = (e < E0) ? tgt[e] : e - E0;
    float ex = __expf(g_sc[i] - fdec(g_smax[t * 2 + hd]));
    g_sc[i] = ex;
    atomicAdd(&g_ssum[t * 2 + hd], ex);
}

// ---------------- alpha-weighted aggregation (warp per aug. edge) ----------
__global__ void k_agg(const int* __restrict__ src, const int* __restrict__ tgt) {
    int e = (blockIdx.x * blockDim.x + threadIdx.x) >> 5;
    int lane = threadIdx.x & 31;
    if (e >= EAUG) return;
    int s, t;
    if (e < E0) { s = src[e]; t = tgt[e]; } else { s = e - E0; t = s; }
    float a0 = g_sc[(size_t)e * 2 + 0] / (g_ssum[t * 2 + 0] + 1e-16f);
    float a1 = g_sc[(size_t)e * 2 + 1] / (g_ssum[t * 2 + 1] + 1e-16f);
    const float* xl = g_xlr + (size_t)s * 128;
    atomicAdd(&g_out[t * 64 + lane],      a0 * xl[lane]);
    atomicAdd(&g_out[t * 64 + 32 + lane], a1 * xl[32 + lane]);
}

// ---------------- h = relu(out + conv_b) -----------------------------------
__global__ void k_nodeh(const float* __restrict__ conv_b) {
    int i = blockIdx.x * blockDim.x + threadIdx.x;
    if (i >= NNODES * 64) return;
    g_h[i] = fmaxf(g_out[i] + __ldg(&conv_b[i & 63]), 0.f);
}

// ---------------------------------------------------------------------------
extern "C" void kernel_launch(void* const* d_in, const int* in_sizes, int n_in,
                              void* d_out, int out_size) {
    const float* x   = (const float*)d_in[0];
    const int*   ei  = (const int*)  d_in[1];
    const float* ea  = (const float*)d_in[2];
    const float* llw = (const float*)d_in[3];
    const float* llb = (const float*)d_in[4];
    const float* lrw = (const float*)d_in[5];
    const float* lrb = (const float*)d_in[6];
    const float* lew = (const float*)d_in[7];
    const float* att = (const float*)d_in[8];
    const float* cb  = (const float*)d_in[9];
    const float* w1  = (const float*)d_in[10];
    const float* b1  = (const float*)d_in[11];
    const float* w2  = (const float*)d_in[12];
    const float* b2  = (const float*)d_in[13];
    float* out = (float*)d_out;

    const int* src = ei;
    const int* tgt = ei + E0;

    k_init<<<2048, 256>>>();

    // xl | xr
    k_gemm<0><<<dim3((NNODES + BM - 1) / BM, 2), 128>>>(
        x, nullptr, nullptr, nullptr, llw, lrw, llb, lrb,
        nullptr, nullptr, nullptr, NNODES, NODE_F);

    // ee over real edges only
    k_gemm<1><<<dim3((E0 + BM - 1) / BM, 1), 128>>>(
        nullptr, ea, nullptr, nullptr, lew, nullptr, nullptr, nullptr,
        nullptr, nullptr, nullptr, E0, EDGE_F);

    // self-loop ee via linearity of the projection
    k_loopee<<<(E0 * 32 + 255) / 256, 256>>>(tgt);
    k_selfdiv<<<(NNODES * 64 + 255) / 256, 256>>>();

    k_score<<<(EAUG * 32 + 255) / 256, 256>>>(src, tgt, att);
    k_expsum<<<(EAUG * 2 + 255) / 256, 256>>>(tgt);
    k_agg<<<(EAUG * 32 + 255) / 256, 256>>>(src, tgt);
    k_nodeh<<<(NNODES * 64 + 255) / 256, 256>>>(cb);

    // per-node precompute: pa = h@W1a, pb = h@W1b
    k_gemm<3><<<dim3((NNODES + BM - 1) / BM, 2), 128>>>(
        nullptr, nullptr, nullptr, nullptr, w1, w1 + 64 * 64, nullptr, nullptr,
        nullptr, nullptr, nullptr, NNODES, 64);

    // fused edge MLP (K=384, q only) -> trust
    k_gemm<2><<<dim3((E0 + BM - 1) / BM, 1), 128>>>(
        nullptr, ea, src, tgt, w1 + 128 * 64, nullptr, b1, nullptr,
        w2, b2, out, E0, 384);
}